// round 17
// baseline (speedup 1.0000x reference)
#include <cuda_runtime.h>
#include <cstdint>
#include <math.h>

#define Hh 512
#define Wd 512
#define Cc 80
#define HW (Hh * Wd)
#define FLATBITS 25
#define FLATMASK ((1u << FLATBITS) - 1)
#define NCHUNK (Cc * (Hh / 8) * 4)   /* 20480 chunks: 8 rows x 128 cols */
#define NBINS 4096
#define HOTC 2048
#define CANDC 3072
#define NEGF (-__builtin_huge_valf())

// ---- global scratch (replay-safe by construction) ----
__device__ unsigned long long g_cm1[NCHUNK];   // fully rewritten each replay
__device__ unsigned int       g_hist[NBINS];   // read-and-zeroed each replay

__device__ __forceinline__ unsigned int fkey(float v) {
    unsigned int u = __float_as_uint(v);
    return (u & 0x80000000u) ? ~u : (u | 0x80000000u);
}
__device__ __forceinline__ float fkey_inv(unsigned int k) {
    unsigned int u = (k & 0x80000000u) ? (k ^ 0x80000000u) : ~k;
    return __uint_as_float(u);
}

// h from already-loaded v + halo scalars. SINGLE implementation shared by both
// passes -> bit-identical fmax sequence -> identical survivor predicates.
__device__ __forceinline__ void hv_from_v(const float4& v, float hl, float hr,
                                          int lane, float4& h) {
    float lft = __shfl_up_sync(0xffffffffu, v.w, 1);
    float rgt = __shfl_down_sync(0xffffffffu, v.x, 1);
    if (lane == 0)  lft = hl;
    if (lane == 31) rgt = hr;
    h.x = fmaxf(fmaxf(lft, v.x), v.y);
    h.y = fmaxf(fmaxf(v.x, v.y), v.z);
    h.z = fmaxf(fmaxf(v.y, v.z), v.w);
    h.w = fmaxf(fmaxf(v.z, v.w), rgt);
}

// Load the 10 rows of chunk (c, y0, g); all loads issued up-front (MLP=10).
__device__ __forceinline__ void load_chunk(const float* __restrict__ base,
                                           int y0, int g, int lane,
                                           float4* __restrict__ vr,
                                           float4* __restrict__ h) {
    float hl[10], hr[10];
    #pragma unroll
    for (int r = 0; r < 10; r++) {
        int yg = y0 - 1 + r;
        bool ok = (yg >= 0) && (yg < Hh);
        const float* row = base + (size_t)(ok ? yg : 0) * Wd;
        if (ok) {
            vr[r] = *(const float4*)(row + g * 128 + lane * 4);
            hl[r] = (lane == 0)  ? ((g > 0) ? row[g * 128 - 1]   : NEGF) : NEGF;
            hr[r] = (lane == 31) ? ((g < 3) ? row[g * 128 + 128] : NEGF) : NEGF;
        } else {
            vr[r].x = vr[r].y = vr[r].z = vr[r].w = NEGF;
            hl[r] = NEGF; hr[r] = NEGF;
        }
    }
    #pragma unroll
    for (int r = 0; r < 10; r++)
        hv_from_v(vr[r], hl[r], hr[r], lane, h[r]);
}

// ---- K1: per-warp chunk NMS -> per-chunk MAX survivor composite. Nothing else. ----
__global__ __launch_bounds__(256) void nms_max_kernel(const float* __restrict__ hmap) {
    const int lane = threadIdx.x & 31, w = threadIdx.x >> 5;
    const unsigned int chunk = blockIdx.x * 8 + w;   // 20480 total
    const int g   = chunk & 3;
    const int ych = (chunk >> 2) & 63;
    const int c   = chunk >> 8;
    const int y0  = ych * 8;
    const float* __restrict__ base = hmap + (size_t)c * HW;

    float4 vr[10], h[10];
    load_chunk(base, y0, g, lane, vr, h);

    unsigned long long m1 = 0ull;   // sentinel; real composites are > 0
    #pragma unroll
    for (int r = 0; r < 8; r++) {
        float4 P = h[r], C = h[r + 1], N = h[r + 2], V = vr[r + 1];
        const unsigned int flrow = (unsigned int)c * HW + (unsigned int)(y0 + r) * Wd
                                 + (unsigned int)(g * 128 + lane * 4);
        float vv[4] = {V.x, V.y, V.z, V.w};
        float mm[4] = {fmaxf(fmaxf(P.x, C.x), N.x),
                       fmaxf(fmaxf(P.y, C.y), N.y),
                       fmaxf(fmaxf(P.z, C.z), N.z),
                       fmaxf(fmaxf(P.w, C.w), N.w)};
        #pragma unroll
        for (int e = 0; e < 4; e++) {
            if (mm[e] == vv[e]) {
                unsigned long long comp =
                    ((unsigned long long)fkey(vv[e]) << FLATBITS)
                  | (unsigned long long)(FLATMASK - (flrow + e));
                m1 = comp > m1 ? comp : m1;
            }
        }
    }
    #pragma unroll
    for (int s = 16; s > 0; s >>= 1) {
        unsigned long long o = __shfl_xor_sync(0xffffffffu, m1, s);
        m1 = o > m1 ? o : m1;
    }
    if (lane == 0) g_cm1[chunk] = m1;
}

// ---- K2: single-block tail — exact threshold, rescan ~K chunks, rank, output ----
__global__ __launch_bounds__(1024) void tail_kernel(const float* __restrict__ hmap,
                                                    const float* __restrict__ regs,
                                                    const float* __restrict__ wh,
                                                    const float* __restrict__ rot,
                                                    float* __restrict__ out, int K) {
    __shared__ unsigned int part[1024];
    __shared__ unsigned int hot[HOTC];
    __shared__ unsigned long long lst[CANDC];
    __shared__ unsigned int s_nlst, s_nhot, s_bin, s_above;
    __shared__ unsigned long long s_T0;
    const int t = threadIdx.x, lane = t & 31, wrp = t >> 5;

    // P1: histogram of cm1 keys (no-return global atomics -> REDG)
    for (int i = t; i < NCHUNK; i += 1024)
        atomicAdd(&g_hist[((unsigned int)(g_cm1[i] >> FLATBITS)) >> 20], 1u);
    if (t == 0) { s_nlst = 0u; s_nhot = 0u; }
    __syncthreads();

    // P2: read + self-clean histogram; suffix scan; pick threshold bin
    unsigned int hb[4];
    #pragma unroll
    for (int j = 0; j < 4; j++) hb[j] = atomicExch(&g_hist[t * 4 + j], 0u);
    part[t] = hb[0] + hb[1] + hb[2] + hb[3];
    __syncthreads();
    for (int d = 1; d < 1024; d <<= 1) {
        unsigned int a = (t + d < 1024) ? part[t + d] : 0u;
        __syncthreads();
        part[t] += a;
        __syncthreads();
    }
    unsigned int cum = (t < 1023) ? part[t + 1] : 0u;
    #pragma unroll
    for (int j = 3; j >= 0; j--) {
        unsigned int nc = cum + hb[j];
        if (nc >= (unsigned int)K && cum < (unsigned int)K) {
            s_bin = (unsigned int)(t * 4 + j);
            s_above = cum;                  // count of cm1 strictly above bin
        }
        cum = nc;
    }
    __syncthreads();
    const unsigned int bin = s_bin, above = s_above;

    // P3: collect bin-b cm1 composites
    for (int i = t; i < NCHUNK; i += 1024) {
        unsigned long long e = g_cm1[i];
        if ((((unsigned int)(e >> FLATBITS)) >> 20) == bin) {
            unsigned int p = atomicAdd(&s_nlst, 1u);
            if (p < CANDC) lst[p] = e;
        }
    }
    __syncthreads();
    const unsigned int nb = min(s_nlst, (unsigned int)CANDC);

    // P4: exact K-th largest cm1 composite = T0
    for (unsigned int i = t; i < nb; i += 1024) {
        unsigned long long e = lst[i];
        unsigned int r = 0;
        for (unsigned int j = 0; j < nb; j++) r += (lst[j] > e) ? 1u : 0u;
        if (above + r == (unsigned int)K - 1) s_T0 = e;
    }
    __syncthreads();
    const unsigned long long T0 = s_T0;
    if (t == 0) s_nlst = 0u;   // lst becomes the candidate buffer
    __syncthreads();

    // P5: hot chunks = { cm1 >= T0 } (exactly K of them)
    for (int i = t; i < NCHUNK; i += 1024) {
        if (g_cm1[i] >= T0) {
            unsigned int p = atomicAdd(&s_nhot, 1u);
            if (p < HOTC) hot[p] = (unsigned int)i;
        }
    }
    __syncthreads();
    const unsigned int nh = min(s_nhot, (unsigned int)HOTC);

    // P6: rescan hot chunks (warp per chunk); emit candidates >= T0
    for (unsigned int wi = wrp; wi < nh; wi += 32) {
        const unsigned int chunk = hot[wi];
        const int g   = chunk & 3;
        const int ych = (chunk >> 2) & 63;
        const int c   = chunk >> 8;
        const int y0  = ych * 8;
        const float* __restrict__ base = hmap + (size_t)c * HW;

        float4 vr[10], h[10];
        load_chunk(base, y0, g, lane, vr, h);

        #pragma unroll
        for (int r = 0; r < 8; r++) {
            float4 P = h[r], C = h[r + 1], N = h[r + 2], V = vr[r + 1];
            const unsigned int flrow = (unsigned int)c * HW
                                     + (unsigned int)(y0 + r) * Wd
                                     + (unsigned int)(g * 128 + lane * 4);
            float vv[4] = {V.x, V.y, V.z, V.w};
            float mm[4] = {fmaxf(fmaxf(P.x, C.x), N.x),
                           fmaxf(fmaxf(P.y, C.y), N.y),
                           fmaxf(fmaxf(P.z, C.z), N.z),
                           fmaxf(fmaxf(P.w, C.w), N.w)};
            #pragma unroll
            for (int e = 0; e < 4; e++) {
                if (mm[e] == vv[e]) {
                    unsigned long long comp =
                        ((unsigned long long)fkey(vv[e]) << FLATBITS)
                      | (unsigned long long)(FLATMASK - (flrow + e));
                    if (comp >= T0) {
                        unsigned int p = atomicAdd(&s_nlst, 1u);
                        if (p < CANDC) lst[p] = comp;
                    }
                }
            }
        }
    }
    __syncthreads();
    const unsigned int n = min(s_nlst, (unsigned int)CANDC);

    // P7: exact rank; gather; write output
    for (unsigned int i = t; i < n; i += 1024) {
        unsigned long long ki = lst[i];
        unsigned int rank = 0;
        for (unsigned int j = 0; j < n; j++) rank += (lst[j] > ki) ? 1u : 0u;
        if (rank < (unsigned int)K) {
            unsigned int key  = (unsigned int)(ki >> FLATBITS);
            unsigned int flat = FLATMASK - (unsigned int)(ki & FLATMASK);
            unsigned int c    = flat / HW;
            unsigned int idx  = flat - c * HW;
            float yf = (float)(idx >> 9);
            float xf = (float)(idx & 511u);
            float vv = fkey_inv(key);
            float score = 1.0f / (1.0f + expf(-vv));
            float* o = out + (size_t)rank * 7;
            o[0] = xf + __ldg(&regs[idx]);
            o[1] = yf + __ldg(&regs[HW + idx]);
            o[2] = __ldg(&wh[idx]);
            o[3] = __ldg(&wh[HW + idx]);
            o[4] = __ldg(&rot[idx]);
            o[5] = score;
            o[6] = (float)c;
        }
    }
}

extern "C" void kernel_launch(void* const* d_in, const int* in_sizes, int n_in,
                              void* d_out, int out_size) {
    const float* hmap = (const float*)d_in[0];
    const float* regs = (const float*)d_in[1];
    const float* wh   = (const float*)d_in[2];
    const float* rot  = (const float*)d_in[3];
    float* out = (float*)d_out;
    int K = out_size / 7;  // B=1; [B,K,7]

    nms_max_kernel<<<NCHUNK / 8, 256>>>(hmap);   // 2560 blocks
    tail_kernel<<<1, 1024>>>(hmap, regs, wh, rot, out, K);
}